// round 6
// baseline (speedup 1.0000x reference)
#include <cuda_runtime.h>
#include <cuda_bf16.h>
#include <cstdint>

#define BATCH   8192
#define KBITS   4096
#define N12     4096
#define N3      1024
#define BN_EPS  1e-5

// GEMM tiling
#define BM      128
#define BN      128
#define BKB     128                 // K bytes (s8 elems) per stage
#define NKIT    (KBITS / BKB)       // 32 k-iterations
#define NSTAGE  4
#define A_STAGE (BM * BKB)          // 16384 B
#define B_STAGE (BN * BKB)          // 16384 B
#define SMEM_TOTAL (NSTAGE * (A_STAGE + B_STAGE))   // 131072

#define SWZ(o) ((o) ^ ((((uint32_t)(o)) >> 3) & 0x70))

// ---------------- device globals (no allocation allowed) -------------------
__device__ int8_t g_A[2][(size_t)BATCH * KBITS];    // ping-pong activations (2 x 32MB)
__device__ int8_t g_W0[(size_t)N12 * KBITS];        // [N][K] s8 (16MB)
__device__ int8_t g_W1[(size_t)N12 * KBITS];
__device__ int8_t g_W2[(size_t)N3  * KBITS];        // 4MB
__device__ int16_t g_s[(size_t)BATCH * N12];        // 64MB, row-major always
__device__ int                 g_colsum[N12];
__device__ unsigned long long  g_colsq[N12];
__device__ int                 g_colmax[N12];
__device__ float               g_rg[N12];
__device__ float               g_Z[N3];
__device__ float               g_invZ[N3];

// ---------------- PTX helpers ---------------------------------------------
#define CP16(dst, src) \
    asm volatile("cp.async.cg.shared.global [%0], [%1], 16;" :: "r"(dst), "l"(src) : "memory")
#define CP_COMMIT() asm volatile("cp.async.commit_group;" ::: "memory")
#define CP_WAIT2()  asm volatile("cp.async.wait_group 2;" ::: "memory")

__device__ __forceinline__ uint32_t smem_u32(const void* p) {
    uint32_t a;
    asm("{ .reg .u64 t; cvta.to.shared.u64 t, %1; cvt.u32.u64 %0, t; }"
        : "=r"(a) : "l"(p));
    return a;
}

__device__ __forceinline__ void imma16832(int* c, const int* a, const int* b) {
    asm volatile(
        "mma.sync.aligned.m16n8k32.row.col.s32.s8.s8.s32 "
        "{%0,%1,%2,%3}, {%4,%5,%6,%7}, {%8,%9}, {%0,%1,%2,%3};"
        : "+r"(c[0]), "+r"(c[1]), "+r"(c[2]), "+r"(c[3])
        : "r"(a[0]), "r"(a[1]), "r"(a[2]), "r"(a[3]),
          "r"(b[0]), "r"(b[1]));
}

__device__ __forceinline__ int wsum8(int v) {   // sum over lanes {tig, tig+4, ..., tig+28}
    v += __shfl_xor_sync(0xFFFFFFFFu, v, 4);
    v += __shfl_xor_sync(0xFFFFFFFFu, v, 8);
    v += __shfl_xor_sync(0xFFFFFFFFu, v, 16);
    return v;
}
__device__ __forceinline__ int wmax8(int v) {
    v = max(v, __shfl_xor_sync(0xFFFFFFFFu, v, 4));
    v = max(v, __shfl_xor_sync(0xFFFFFFFFu, v, 8));
    v = max(v, __shfl_xor_sync(0xFFFFFFFFu, v, 16));
    return v;
}

// ---------------- binarize x -> s8 +-1 (x >= 0.5) --------------------------
__global__ void bp_binx(const float* __restrict__ x) {
    size_t i = ((size_t)blockIdx.x * blockDim.x + threadIdx.x) * 4;
    float4 v = *(const float4*)&x[i];
    uint32_t o = (uint32_t)(uint8_t)(int8_t)(v.x >= 0.5f ? 1 : -1)
               | ((uint32_t)(uint8_t)(int8_t)(v.y >= 0.5f ? 1 : -1) << 8)
               | ((uint32_t)(uint8_t)(int8_t)(v.z >= 0.5f ? 1 : -1) << 16)
               | ((uint32_t)(uint8_t)(int8_t)(v.w >= 0.5f ? 1 : -1) << 24);
    *(uint32_t*)&g_A[0][i] = o;
}

// ---------------- binarize + transpose W -> s8 +-1 [N][K] ------------------
__global__ void bp_binw(const float* __restrict__ W, int which, int N) {
    __shared__ float tile[32][33];
    int j0 = blockIdx.x * 32, k0 = blockIdx.y * 32;
    tile[threadIdx.y][threadIdx.x] = W[(size_t)(k0 + threadIdx.y) * N + j0 + threadIdx.x];
    __syncthreads();
    float v = tile[threadIdx.x][threadIdx.y];   // element (k0+tx, j0+ty)
    int8_t* Wt = (which == 0) ? g_W0 : (which == 1) ? g_W1 : g_W2;
    Wt[(size_t)(j0 + threadIdx.y) * KBITS + k0 + threadIdx.x] = (v >= 0.f) ? 1 : -1;
}

// ---------------- zero stats ----------------------------------------------
__global__ void bp_zero(int n) {
    int i = blockIdx.x * blockDim.x + threadIdx.x;
    if (i < n) { g_colsum[i] = 0; g_colsq[i] = 0ull; g_colmax[i] = (int)0x80000000; }
    if (i < N3) g_Z[i] = 0.f;
}

// ---------------- s8 IMMA GEMM + fused column stats ------------------------
// C[BM=128, BN=128] = A[m0:, :] * B[n0:, :]^T, K=4096, all-+-1 s8, exact s32.
__global__ __launch_bounds__(256, 1) void bp_imma(int asel, int wsel, int N, int l3) {
    extern __shared__ char smem[];
    int tid = threadIdx.x, wid = tid >> 5, lane = tid & 31;
    int grp = lane >> 2, tig = lane & 3;
    int wm = wid >> 2, wn = wid & 3;            // 2 x 4 warp grid

    const int8_t* A = g_A[asel];
    const int8_t* B = (wsel == 0) ? g_W0 : (wsel == 1) ? g_W1 : g_W2;
    int m0 = blockIdx.y * BM, n0 = blockIdx.x * BN;
    const char* gA = (const char*)(A + (size_t)m0 * KBITS);
    const char* gB = (const char*)(B + (size_t)n0 * KBITS);

    int acc[4][4][4];
#pragma unroll
    for (int mi = 0; mi < 4; mi++)
#pragma unroll
        for (int ni = 0; ni < 4; ni++)
#pragma unroll
            for (int r = 0; r < 4; r++) acc[mi][ni][r] = 0;

    // producer lambda: load stage s of k-iter kt
    int lr = tid >> 3, lw = tid & 7;            // row-pair base, 16B col
    auto load_stage = [&](int kt) {
        int st = kt & (NSTAGE - 1);
        char* sA = smem + st * A_STAGE;
        char* sB = smem + NSTAGE * A_STAGE + st * B_STAGE;
        size_t kb = (size_t)kt * BKB;
#pragma unroll
        for (int e = 0; e < 4; e++) {           // A: 1024 16B units
            int r = lr + e * 32;
            uint32_t dst = smem_u32(sA + r * BKB + ((lw * 16) ^ ((r & 7) << 4)));
            CP16(dst, gA + (size_t)r * KBITS + kb + lw * 16);
        }
#pragma unroll
        for (int e = 0; e < 4; e++) {           // B: 1024 16B units
            int r = lr + e * 32;
            uint32_t dst = smem_u32(sB + r * BKB + ((lw * 16) ^ ((r & 7) << 4)));
            CP16(dst, gB + (size_t)r * KBITS + kb + lw * 16);
        }
    };

    // prologue: stages 0..2
#pragma unroll
    for (int kt = 0; kt < NSTAGE - 1; kt++) { load_stage(kt); CP_COMMIT(); }

    for (int kt = 0; kt < NKIT; kt++) {
        CP_WAIT2();
        __syncthreads();
        if (kt + NSTAGE - 1 < NKIT) load_stage(kt + NSTAGE - 1);
        CP_COMMIT();

        int st = kt & (NSTAGE - 1);
        const char* sA = smem + st * A_STAGE;
        const char* sB = smem + NSTAGE * A_STAGE + st * B_STAGE;
#pragma unroll
        for (int kk = 0; kk < BKB; kk += 32) {
            int a[4][4], b[4][2];
#pragma unroll
            for (int mi = 0; mi < 4; mi++)
#pragma unroll
                for (int r = 0; r < 4; r++) {
                    int row = wm * 64 + mi * 16 + grp + ((r & 1) << 3);
                    int kb2 = kk + ((r >> 1) << 4) + tig * 4;
                    a[mi][r] = *(const int*)(sA + row * BKB + (kb2 ^ ((row & 7) << 4)));
                }
#pragma unroll
            for (int ni = 0; ni < 4; ni++)
#pragma unroll
                for (int r = 0; r < 2; r++) {
                    int row = wn * 32 + ni * 8 + grp;
                    int kb2 = kk + (r << 4) + tig * 4;
                    b[ni][r] = *(const int*)(sB + row * BKB + (kb2 ^ ((row & 7) << 4)));
                }
#pragma unroll
            for (int mi = 0; mi < 4; mi++)
#pragma unroll
                for (int ni = 0; ni < 4; ni++)
                    imma16832(acc[mi][ni], a[mi], b[ni]);
        }
        __syncthreads();
    }

    // ---------------- epilogue: write s (int16, row-major) + stats ---------
#pragma unroll
    for (int mi = 0; mi < 4; mi++) {
        int r0 = m0 + wm * 64 + mi * 16 + grp;
#pragma unroll
        for (int ni = 0; ni < 4; ni++) {
            int c0 = n0 + wn * 32 + ni * 8 + tig * 2;
            int* v = acc[mi][ni];
            *(uint32_t*)&g_s[(size_t)r0 * N + c0] =
                (uint32_t)(uint16_t)(int16_t)v[0] | ((uint32_t)(uint16_t)(int16_t)v[1] << 16);
            *(uint32_t*)&g_s[(size_t)(r0 + 8) * N + c0] =
                (uint32_t)(uint16_t)(int16_t)v[2] | ((uint32_t)(uint16_t)(int16_t)v[3] << 16);
        }
    }
    // column stats: per ni, columns (tig*2, tig*2+1); accumulate over 4 m-frags
#pragma unroll
    for (int ni = 0; ni < 4; ni++) {
        int s0 = 0, s1 = 0, q0 = 0, q1 = 0, x0 = (int)0x80000000, x1 = (int)0x80000000;
#pragma unroll
        for (int mi = 0; mi < 4; mi++) {
            int* v = acc[mi][ni];
            s0 += v[0] + v[2];          s1 += v[1] + v[3];
            q0 += v[0]*v[0] + v[2]*v[2]; q1 += v[1]*v[1] + v[3]*v[3];
            x0 = max(x0, max(v[0], v[2])); x1 = max(x1, max(v[1], v[3]));
        }
        s0 = wsum8(s0); s1 = wsum8(s1);
        q0 = wsum8(q0); q1 = wsum8(q1);
        if (l3) { x0 = wmax8(x0); x1 = wmax8(x1); }
        if (grp == 0) {
            int col = n0 + wn * 32 + ni * 8 + tig * 2;
            atomicAdd(&g_colsum[col],     s0);
            atomicAdd(&g_colsum[col + 1], s1);
            atomicAdd(&g_colsq[col],     (unsigned long long)(long long)q0);
            atomicAdd(&g_colsq[col + 1], (unsigned long long)(long long)q1);
            if (l3) {
                atomicMax(&g_colmax[col],     x0);
                atomicMax(&g_colmax[col + 1], x1);
            }
        }
    }
}

// ---------------- per-column rg = gamma * rsqrt(var+eps) -------------------
__global__ void bp_colprep(int N, const float* __restrict__ gamma, int layer) {
    int j = blockIdx.x * blockDim.x + threadIdx.x;
    if (j < N) {
        double mu  = (double)g_colsum[j] / (double)BATCH;
        double var = (double)g_colsq[j] / (double)BATCH - mu * mu;
        g_rg[j] = (float)((double)gamma[layer] / sqrt(var + BN_EPS));
    }
}

// ---------------- binarize normalized activations -> s8 +-1 ----------------
// sign((s*B - colsum)*rg + beta*B); exact for beta = 0.
__global__ void bp_bins(int N, int dst, const float* __restrict__ beta, int layer) {
    size_t i = ((size_t)blockIdx.x * blockDim.x + threadIdx.x) * 8;
    int col0 = (int)(i & (size_t)(N - 1));
    uint4 sp = *(const uint4*)&g_s[i];
    int sv[8];
    sv[0] = (int)(int16_t)(sp.x & 0xFFFF); sv[1] = (int)(int16_t)(sp.x >> 16);
    sv[2] = (int)(int16_t)(sp.y & 0xFFFF); sv[3] = (int)(int16_t)(sp.y >> 16);
    sv[4] = (int)(int16_t)(sp.z & 0xFFFF); sv[5] = (int)(int16_t)(sp.z >> 16);
    sv[6] = (int)(int16_t)(sp.w & 0xFFFF); sv[7] = (int)(int16_t)(sp.w >> 16);
    float b = beta[layer] * (float)BATCH;
    uint32_t h[8];
#pragma unroll
    for (int e = 0; e < 8; e++) {
        int num = sv[e] * BATCH - g_colsum[col0 + e];
        float v = (float)num * g_rg[col0 + e] + b;
        h[e] = (uint32_t)(uint8_t)(int8_t)((v >= 0.f) ? 1 : -1);
    }
    uint2 o;
    o.x = h[0] | (h[1] << 8) | (h[2] << 16) | (h[3] << 24);
    o.y = h[4] | (h[5] << 8) | (h[6] << 16) | (h[7] << 24);
    *(uint2*)&g_A[dst][i] = o;
}

// ---------------- softmax partial sums (s row-major) -----------------------
__global__ void bp_softz() {                    // grid 256, block 256
    int r0 = blockIdx.x * 32;
    int t = threadIdx.x;
    float rg[4], acc[4];
    int   mx[4];
#pragma unroll
    for (int q = 0; q < 4; q++) {
        rg[q]  = g_rg[t + q * 256];
        mx[q]  = g_colmax[t + q * 256];
        acc[q] = 0.f;
    }
    for (int r = r0; r < r0 + 32; r++) {
        const int16_t* row = &g_s[(size_t)r * N3];
#pragma unroll
        for (int q = 0; q < 4; q++)
            acc[q] += expf(rg[q] * (float)(row[t + q * 256] - mx[q]));
    }
#pragma unroll
    for (int q = 0; q < 4; q++) atomicAdd(&g_Z[t + q * 256], acc[q]);
}

__global__ void bp_invz() {
    int j = blockIdx.x * blockDim.x + threadIdx.x;
    if (j < N3) g_invZ[j] = 1.f / g_Z[j];
}

// ---------------- writeout (row-major, fully coalesced) --------------------
__global__ void bp_writeout(float* __restrict__ out) {
    size_t e = (size_t)blockIdx.x * blockDim.x + threadIdx.x;
    int j = (int)(e & (N3 - 1));
    out[e] = expf(g_rg[j] * (float)(g_s[e] - g_colmax[j])) * g_invZ[j];
}

// ---------------- launch ---------------------------------------------------
extern "C" void kernel_launch(void* const* d_in, const int* in_sizes, int n_in,
                              void* d_out, int out_size) {
    const float* x     = (const float*)d_in[0];
    const float* W0    = (const float*)d_in[1];
    const float* W1    = (const float*)d_in[2];
    const float* W2    = (const float*)d_in[3];
    const float* gamma = (const float*)d_in[4];
    const float* beta  = (const float*)d_in[5];
    float* out = (float*)d_out;

    cudaFuncSetAttribute(bp_imma, cudaFuncAttributeMaxDynamicSharedMemorySize, SMEM_TOTAL);

    dim3 b32(32, 32);
    bp_binx<<<(BATCH * KBITS / 4) / 256, 256>>>(x);
    bp_binw<<<dim3(N12 / 32, KBITS / 32), b32>>>(W0, 0, N12);
    bp_binw<<<dim3(N12 / 32, KBITS / 32), b32>>>(W1, 1, N12);
    bp_binw<<<dim3(N3  / 32, KBITS / 32), b32>>>(W2, 2, N3);

    // ---- layer 0 ----
    bp_zero<<<N12 / 256, 256>>>(N12);
    bp_imma<<<dim3(N12 / BN, BATCH / BM), 256, SMEM_TOTAL>>>(0, 0, N12, 0);
    bp_colprep<<<N12 / 256, 256>>>(N12, gamma, 0);
    bp_bins<<<(BATCH * N12 / 8) / 256, 256>>>(N12, 1, beta, 0);

    // ---- layer 1 ----
    bp_zero<<<N12 / 256, 256>>>(N12);
    bp_imma<<<dim3(N12 / BN, BATCH / BM), 256, SMEM_TOTAL>>>(1, 1, N12, 0);
    bp_colprep<<<N12 / 256, 256>>>(N12, gamma, 1);
    bp_bins<<<(BATCH * N12 / 8) / 256, 256>>>(N12, 0, beta, 1);

    // ---- layer 2 (row-major s, +colmax) ----
    bp_zero<<<N12 / 256, 256>>>(N12);
    bp_imma<<<dim3(N3 / BN, BATCH / BM), 256, SMEM_TOTAL>>>(0, 2, N3, 1);
    bp_colprep<<<N3 / 256, 256>>>(N3, gamma, 2);
    bp_softz<<<256, 256>>>();
    bp_invz<<<N3 / 256, 256>>>();
    bp_writeout<<<(BATCH * N3) / 256, 256>>>(out);
}

// round 7
// speedup vs baseline: 2.2828x; 2.2828x over previous
#include <cuda_runtime.h>
#include <cuda_bf16.h>
#include <cstdint>

#define BATCH   8192
#define KBITS   4096
#define N12     4096
#define N3      1024
#define BN_EPS  1e-5

// GEMM tiling
#define BM      128
#define BN      128
#define BK      64                  // K elems (bf16) per stage = 128 B rows
#define NKIT    (KBITS / BK)        // 64 k-iterations
#define NSTAGE  6
#define A_STAGE (BM * 128)          // 16384 B
#define B_STAGE (BN * 128)          // 16384 B
#define SMEM_TOTAL (NSTAGE * (A_STAGE + B_STAGE))   // 196608

// ---------------- device globals (no allocation allowed) -------------------
__device__ __nv_bfloat16 g_A[2][(size_t)BATCH * KBITS];   // ping-pong activations (2 x 64MB)
__device__ __nv_bfloat16 g_W0[(size_t)N12 * KBITS];       // [N][K] bf16 (32MB)
__device__ __nv_bfloat16 g_W1[(size_t)N12 * KBITS];
__device__ __nv_bfloat16 g_W2[(size_t)N3  * KBITS];       // 8MB
__device__ int16_t g_s[(size_t)BATCH * N12];              // 64MB, row-major always
__device__ int                 g_colsum[N12];
__device__ unsigned long long  g_colsq[N12];
__device__ int                 g_colmax[N12];
__device__ float               g_rg[N12];
__device__ float               g_Z[N3];
__device__ float               g_invZ[N3];

// ---------------- PTX helpers ---------------------------------------------
#define CP16(dst, src) \
    asm volatile("cp.async.cg.shared.global [%0], [%1], 16;" :: "r"(dst), "l"(src) : "memory")
#define CP_COMMIT() asm volatile("cp.async.commit_group;" ::: "memory")
#define CP_WAIT4()  asm volatile("cp.async.wait_group 4;" ::: "memory")

__device__ __forceinline__ uint32_t smem_u32(const void* p) {
    uint32_t a;
    asm("{ .reg .u64 t; cvta.to.shared.u64 t, %1; cvt.u32.u64 %0, t; }"
        : "=r"(a) : "l"(p));
    return a;
}

#define LDSM_X4(r, addr) \
    asm volatile("ldmatrix.sync.aligned.m8n8.x4.shared.b16 {%0,%1,%2,%3}, [%4];" \
        : "=r"((r)[0]), "=r"((r)[1]), "=r"((r)[2]), "=r"((r)[3]) : "r"(addr))

__device__ __forceinline__ void hmma(float* c, const uint32_t* a,
                                     uint32_t b0, uint32_t b1) {
    asm volatile(
        "mma.sync.aligned.m16n8k16.row.col.f32.bf16.bf16.f32 "
        "{%0,%1,%2,%3}, {%4,%5,%6,%7}, {%8,%9}, {%0,%1,%2,%3};"
        : "+f"(c[0]), "+f"(c[1]), "+f"(c[2]), "+f"(c[3])
        : "r"(a[0]), "r"(a[1]), "r"(a[2]), "r"(a[3]), "r"(b0), "r"(b1));
}

__device__ __forceinline__ int wsum8(int v) {   // sum over grp 0..7 (fixed tig)
    v += __shfl_xor_sync(0xFFFFFFFFu, v, 4);
    v += __shfl_xor_sync(0xFFFFFFFFu, v, 8);
    v += __shfl_xor_sync(0xFFFFFFFFu, v, 16);
    return v;
}
__device__ __forceinline__ int wmax8(int v) {
    v = max(v, __shfl_xor_sync(0xFFFFFFFFu, v, 4));
    v = max(v, __shfl_xor_sync(0xFFFFFFFFu, v, 8));
    v = max(v, __shfl_xor_sync(0xFFFFFFFFu, v, 16));
    return v;
}

// ---------------- binarize x -> bf16 +-1 (x >= 0.5) ------------------------
__global__ void bp_binx(const float* __restrict__ x) {
    size_t i = ((size_t)blockIdx.x * blockDim.x + threadIdx.x) * 4;
    float4 v = *(const float4*)&x[i];
    uint32_t p = 0x3F80u, n = 0xBF80u;
    uint2 o;
    o.x = (v.x >= 0.5f ? p : n) | ((v.y >= 0.5f ? p : n) << 16);
    o.y = (v.z >= 0.5f ? p : n) | ((v.w >= 0.5f ? p : n) << 16);
    *(uint2*)&g_A[0][i] = o;
}

// ---------------- binarize + transpose W -> bf16 +-1 [N][K] ----------------
__global__ void bp_binw(const float* __restrict__ W, int which, int N) {
    __shared__ float tile[32][33];
    int j0 = blockIdx.x * 32, k0 = blockIdx.y * 32;
    tile[threadIdx.y][threadIdx.x] = W[(size_t)(k0 + threadIdx.y) * N + j0 + threadIdx.x];
    __syncthreads();
    float v = tile[threadIdx.x][threadIdx.y];   // element (k0+tx, j0+ty)
    __nv_bfloat16* Wt = (which == 0) ? g_W0 : (which == 1) ? g_W1 : g_W2;
    *(uint16_t*)&Wt[(size_t)(j0 + threadIdx.y) * KBITS + k0 + threadIdx.x] =
        (v >= 0.f) ? 0x3F80u : 0xBF80u;
}

// ---------------- zero stats ----------------------------------------------
__global__ void bp_zero(int n) {
    int i = blockIdx.x * blockDim.x + threadIdx.x;
    if (i < n) { g_colsum[i] = 0; g_colsq[i] = 0ull; g_colmax[i] = (int)0x80000000; }
    if (i < N3) g_Z[i] = 0.f;
}

// ---------------- bf16 HMMA GEMM + fused column stats ----------------------
// C[BM=128, BN=128] = A[m0:, :] * B[n0:, :]^T, K=4096, all-+-1, exact in f32.
__global__ __launch_bounds__(256, 1) void bp_hmma(int asel, int wsel, int N, int l3) {
    extern __shared__ char smem[];
    uint32_t sbase = smem_u32(smem);
    int tid = threadIdx.x, wid = tid >> 5, lane = tid & 31;
    int grp = lane >> 2, tig = lane & 3;
    int wm = wid >> 2, wn = wid & 3;            // 2 x 4 warp grid -> warp tile 64x32
    int sel = lane >> 3, ilane = lane & 7;

    const __nv_bfloat16* A = g_A[asel];
    const __nv_bfloat16* B = (wsel == 0) ? g_W0 : (wsel == 1) ? g_W1 : g_W2;
    int m0 = blockIdx.y * BM, n0 = blockIdx.x * BN;
    const char* gA = (const char*)(A + (size_t)m0 * KBITS);
    const char* gB = (const char*)(B + (size_t)n0 * KBITS);

    // per-lane ldmatrix offsets (within a stage)
    uint32_t offA = (uint32_t)(wm * 64 + (sel & 1) * 8 + ilane) * 128;
    uint32_t c0a  = (uint32_t)(sel >> 1);
    uint32_t offB = (uint32_t)(wn * 32 + (sel >> 1) * 8 + ilane) * 128;
    uint32_t c0b  = (uint32_t)(sel & 1);

    float acc[4][4][4];
#pragma unroll
    for (int mi = 0; mi < 4; mi++)
#pragma unroll
        for (int ni = 0; ni < 4; ni++)
#pragma unroll
            for (int r = 0; r < 4; r++) acc[mi][ni][r] = 0.f;

    int lr = tid >> 3, lw = tid & 7;            // cp.async: row, 16B col
    auto load_stage = [&](int kt) {
        int st = kt % NSTAGE;
        uint32_t sA = sbase + st * A_STAGE;
        uint32_t sB = sbase + NSTAGE * A_STAGE + st * B_STAGE;
        size_t kb = (size_t)kt * 128;           // BK bf16 = 128 bytes
#pragma unroll
        for (int e = 0; e < 4; e++) {
            int r = lr + e * 32;
            uint32_t sw = (uint32_t)((lw * 16) ^ ((r & 7) << 4));
            CP16(sA + r * 128 + sw, gA + (size_t)r * (KBITS * 2) + kb + lw * 16);
            CP16(sB + r * 128 + sw, gB + (size_t)r * (KBITS * 2) + kb + lw * 16);
        }
    };

#pragma unroll
    for (int kt = 0; kt < NSTAGE - 1; kt++) { load_stage(kt); CP_COMMIT(); }

    for (int kt = 0; kt < NKIT; kt++) {
        CP_WAIT4();
        __syncthreads();
        if (kt + NSTAGE - 1 < NKIT) load_stage(kt + NSTAGE - 1);
        CP_COMMIT();

        int st = kt % NSTAGE;
        uint32_t sA = sbase + st * A_STAGE;
        uint32_t sB = sbase + NSTAGE * A_STAGE + st * B_STAGE;
#pragma unroll
        for (int k16 = 0; k16 < 4; k16++) {
            uint32_t ca = ((c0a + 2 * k16) ^ (uint32_t)ilane) << 4;
            uint32_t cb = ((c0b + 2 * k16) ^ (uint32_t)ilane) << 4;
            uint32_t a[4][4], b[2][4];
#pragma unroll
            for (int mi = 0; mi < 4; mi++)
                LDSM_X4(a[mi], sA + offA + mi * 2048 + ca);
#pragma unroll
            for (int nb = 0; nb < 2; nb++)
                LDSM_X4(b[nb], sB + offB + nb * 2048 + cb);
#pragma unroll
            for (int mi = 0; mi < 4; mi++) {
                hmma(acc[mi][0], a[mi], b[0][0], b[0][1]);
                hmma(acc[mi][1], a[mi], b[0][2], b[0][3]);
                hmma(acc[mi][2], a[mi], b[1][0], b[1][1]);
                hmma(acc[mi][3], a[mi], b[1][2], b[1][3]);
            }
        }
        __syncthreads();
    }

    // ---------------- epilogue: write s (int16, row-major) + stats ---------
    int iv[4][4][4];
#pragma unroll
    for (int mi = 0; mi < 4; mi++)
#pragma unroll
        for (int ni = 0; ni < 4; ni++)
#pragma unroll
            for (int r = 0; r < 4; r++)
                iv[mi][ni][r] = __float2int_rn(acc[mi][ni][r]);

#pragma unroll
    for (int mi = 0; mi < 4; mi++) {
        int r0 = m0 + wm * 64 + mi * 16 + grp;
#pragma unroll
        for (int ni = 0; ni < 4; ni++) {
            int c0 = n0 + wn * 32 + ni * 8 + tig * 2;
            int* v = iv[mi][ni];
            *(uint32_t*)&g_s[(size_t)r0 * N + c0] =
                (uint32_t)(uint16_t)(int16_t)v[0] | ((uint32_t)(uint16_t)(int16_t)v[1] << 16);
            *(uint32_t*)&g_s[(size_t)(r0 + 8) * N + c0] =
                (uint32_t)(uint16_t)(int16_t)v[2] | ((uint32_t)(uint16_t)(int16_t)v[3] << 16);
        }
    }
#pragma unroll
    for (int ni = 0; ni < 4; ni++) {
        int s0 = 0, s1 = 0, q0 = 0, q1 = 0, x0 = (int)0x80000000, x1 = (int)0x80000000;
#pragma unroll
        for (int mi = 0; mi < 4; mi++) {
            int* v = iv[mi][ni];
            s0 += v[0] + v[2];           s1 += v[1] + v[3];
            q0 += v[0]*v[0] + v[2]*v[2]; q1 += v[1]*v[1] + v[3]*v[3];
            x0 = max(x0, max(v[0], v[2])); x1 = max(x1, max(v[1], v[3]));
        }
        s0 = wsum8(s0); s1 = wsum8(s1);
        q0 = wsum8(q0); q1 = wsum8(q1);
        if (l3) { x0 = wmax8(x0); x1 = wmax8(x1); }
        if (grp == 0) {
            int col = n0 + wn * 32 + ni * 8 + tig * 2;
            atomicAdd(&g_colsum[col],     s0);
            atomicAdd(&g_colsum[col + 1], s1);
            atomicAdd(&g_colsq[col],     (unsigned long long)(long long)q0);
            atomicAdd(&g_colsq[col + 1], (unsigned long long)(long long)q1);
            if (l3) {
                atomicMax(&g_colmax[col],     x0);
                atomicMax(&g_colmax[col + 1], x1);
            }
        }
    }
}

// ---------------- per-column rg = gamma * rsqrt(var+eps) -------------------
__global__ void bp_colprep(int N, const float* __restrict__ gamma, int layer) {
    int j = blockIdx.x * blockDim.x + threadIdx.x;
    if (j < N) {
        double mu  = (double)g_colsum[j] / (double)BATCH;
        double var = (double)g_colsq[j] / (double)BATCH - mu * mu;
        g_rg[j] = (float)((double)gamma[layer] / sqrt(var + BN_EPS));
    }
}

// ---------------- binarize normalized activations -> bf16 +-1 --------------
// sign((s*B - colsum)*rg + beta*B); exact for beta = 0.
__global__ void bp_bins(int N, int dst, const float* __restrict__ beta, int layer) {
    size_t i = ((size_t)blockIdx.x * blockDim.x + threadIdx.x) * 8;
    int col0 = (int)(i & (size_t)(N - 1));
    uint4 sp = *(const uint4*)&g_s[i];
    int sv[8];
    sv[0] = (int)(int16_t)(sp.x & 0xFFFF); sv[1] = (int)(int16_t)(sp.x >> 16);
    sv[2] = (int)(int16_t)(sp.y & 0xFFFF); sv[3] = (int)(int16_t)(sp.y >> 16);
    sv[4] = (int)(int16_t)(sp.z & 0xFFFF); sv[5] = (int)(int16_t)(sp.z >> 16);
    sv[6] = (int)(int16_t)(sp.w & 0xFFFF); sv[7] = (int)(int16_t)(sp.w >> 16);
    float b = beta[layer] * (float)BATCH;
    uint32_t h[8];
#pragma unroll
    for (int e = 0; e < 8; e++) {
        int num = sv[e] * BATCH - g_colsum[col0 + e];
        float v = (float)num * g_rg[col0 + e] + b;
        h[e] = (v >= 0.f) ? 0x3F80u : 0xBF80u;
    }
    uint4 o;
    o.x = h[0] | (h[1] << 16); o.y = h[2] | (h[3] << 16);
    o.z = h[4] | (h[5] << 16); o.w = h[6] | (h[7] << 16);
    *(uint4*)&g_A[dst][i] = o;
}

// ---------------- softmax partial sums (s row-major) -----------------------
__global__ void bp_softz() {                    // grid 256, block 256
    int r0 = blockIdx.x * 32;
    int t = threadIdx.x;
    float rg[4], acc[4];
    int   mx[4];
#pragma unroll
    for (int q = 0; q < 4; q++) {
        rg[q]  = g_rg[t + q * 256];
        mx[q]  = g_colmax[t + q * 256];
        acc[q] = 0.f;
    }
    for (int r = r0; r < r0 + 32; r++) {
        const int16_t* row = &g_s[(size_t)r * N3];
#pragma unroll
        for (int q = 0; q < 4; q++)
            acc[q] += expf(rg[q] * (float)(row[t + q * 256] - mx[q]));
    }
#pragma unroll
    for (int q = 0; q < 4; q++) atomicAdd(&g_Z[t + q * 256], acc[q]);
}

__global__ void bp_invz() {
    int j = blockIdx.x * blockDim.x + threadIdx.x;
    if (j < N3) g_invZ[j] = 1.f / g_Z[j];
}

// ---------------- writeout (row-major, fully coalesced) --------------------
__global__ void bp_writeout(float* __restrict__ out) {
    size_t e = (size_t)blockIdx.x * blockDim.x + threadIdx.x;
    int j = (int)(e & (N3 - 1));
    out[e] = expf(g_rg[j] * (float)(g_s[e] - g_colmax[j])) * g_invZ[j];
}

// ---------------- launch ---------------------------------------------------
extern "C" void kernel_launch(void* const* d_in, const int* in_sizes, int n_in,
                              void* d_out, int out_size) {
    const float* x     = (const float*)d_in[0];
    const float* W0    = (const float*)d_in[1];
    const float* W1    = (const float*)d_in[2];
    const float* W2    = (const float*)d_in[3];
    const float* gamma = (const float*)d_in[4];
    const float* beta  = (const float*)d_in[5];
    float* out = (float*)d_out;

    cudaFuncSetAttribute(bp_hmma, cudaFuncAttributeMaxDynamicSharedMemorySize, SMEM_TOTAL);

    dim3 b32(32, 32);
    bp_binx<<<(BATCH * KBITS / 4) / 256, 256>>>(x);
    bp_binw<<<dim3(N12 / 32, KBITS / 32), b32>>>(W0, 0, N12);
    bp_binw<<<dim3(N12 / 32, KBITS / 32), b32>>>(W1, 1, N12);
    bp_binw<<<dim3(N3  / 32, KBITS / 32), b32>>>(W2, 2, N3);

    // ---- layer 0 ----
    bp_zero<<<N12 / 256, 256>>>(N12);
    bp_hmma<<<dim3(N12 / BN, BATCH / BM), 256, SMEM_TOTAL>>>(0, 0, N12, 0);
    bp_colprep<<<N12 / 256, 256>>>(N12, gamma, 0);
    bp_bins<<<(BATCH * N12 / 8) / 256, 256>>>(N12, 1, beta, 0);

    // ---- layer 1 ----
    bp_zero<<<N12 / 256, 256>>>(N12);
    bp_hmma<<<dim3(N12 / BN, BATCH / BM), 256, SMEM_TOTAL>>>(1, 1, N12, 0);
    bp_colprep<<<N12 / 256, 256>>>(N12, gamma, 1);
    bp_bins<<<(BATCH * N12 / 8) / 256, 256>>>(N12, 0, beta, 1);

    // ---- layer 2 (row-major s, +colmax) ----
    bp_zero<<<N12 / 256, 256>>>(N12);
    bp_hmma<<<dim3(N3 / BN, BATCH / BM), 256, SMEM_TOTAL>>>(0, 2, N3, 1);
    bp_colprep<<<N3 / 256, 256>>>(N3, gamma, 2);
    bp_softz<<<256, 256>>>();
    bp_invz<<<N3 / 256, 256>>>();
    bp_writeout<<<(BATCH * N3) / 256, 256>>>(out);
}

// round 8
// speedup vs baseline: 2.4343x; 1.0664x over previous
#include <cuda_runtime.h>
#include <cuda_bf16.h>
#include <cstdint>

#define BATCH   8192
#define KBITS   4096
#define N12     4096
#define N3      1024
#define BN_EPS  1e-5

// GEMM tiling
#define BM      256
#define BN      128
#define BK      64                  // K elems (bf16) per stage = 128 B rows
#define NKIT    (KBITS / BK)        // 64 k-iterations
#define NSTAGE  4
#define A_STAGE (BM * 128)          // 32768 B
#define B_STAGE (BN * 128)          // 16384 B
#define SMEM_TOTAL (NSTAGE * (A_STAGE + B_STAGE))   // 196608

// ---------------- device globals (no allocation allowed) -------------------
__device__ __nv_bfloat16 g_A[2][(size_t)BATCH * KBITS];   // ping-pong activations (2 x 64MB)
__device__ __nv_bfloat16 g_W0[(size_t)N12 * KBITS];       // [N][K] bf16 (32MB)
__device__ __nv_bfloat16 g_W1[(size_t)N12 * KBITS];
__device__ __nv_bfloat16 g_W2[(size_t)N3  * KBITS];       // 8MB
__device__ int16_t g_s[(size_t)BATCH * N12];              // 64MB, row-major always
__device__ int                 g_colsum[N12];
__device__ unsigned long long  g_colsq[N12];
__device__ int                 g_colmax[N12];
__device__ float               g_rg[N12];
__device__ float               g_Z[N3];
__device__ float               g_invZ[N3];

// ---------------- PTX helpers ---------------------------------------------
#define CP16(dst, src) \
    asm volatile("cp.async.cg.shared.global [%0], [%1], 16;" :: "r"(dst), "l"(src) : "memory")
#define CP_COMMIT() asm volatile("cp.async.commit_group;" ::: "memory")
#define CP_WAIT2()  asm volatile("cp.async.wait_group 2;" ::: "memory")

__device__ __forceinline__ uint32_t smem_u32(const void* p) {
    uint32_t a;
    asm("{ .reg .u64 t; cvta.to.shared.u64 t, %1; cvt.u32.u64 %0, t; }"
        : "=r"(a) : "l"(p));
    return a;
}

#define LDSM_X4(r, addr) \
    asm volatile("ldmatrix.sync.aligned.m8n8.x4.shared.b16 {%0,%1,%2,%3}, [%4];" \
        : "=r"((r)[0]), "=r"((r)[1]), "=r"((r)[2]), "=r"((r)[3]) : "r"(addr))

__device__ __forceinline__ void hmma(float* c, const uint32_t* a,
                                     uint32_t b0, uint32_t b1) {
    asm volatile(
        "mma.sync.aligned.m16n8k16.row.col.f32.bf16.bf16.f32 "
        "{%0,%1,%2,%3}, {%4,%5,%6,%7}, {%8,%9}, {%0,%1,%2,%3};"
        : "+f"(c[0]), "+f"(c[1]), "+f"(c[2]), "+f"(c[3])
        : "r"(a[0]), "r"(a[1]), "r"(a[2]), "r"(a[3]), "r"(b0), "r"(b1));
}

__device__ __forceinline__ int wsum8(int v) {
    v += __shfl_xor_sync(0xFFFFFFFFu, v, 4);
    v += __shfl_xor_sync(0xFFFFFFFFu, v, 8);
    v += __shfl_xor_sync(0xFFFFFFFFu, v, 16);
    return v;
}
__device__ __forceinline__ int wmax8(int v) {
    v = max(v, __shfl_xor_sync(0xFFFFFFFFu, v, 4));
    v = max(v, __shfl_xor_sync(0xFFFFFFFFu, v, 8));
    v = max(v, __shfl_xor_sync(0xFFFFFFFFu, v, 16));
    return v;
}

// ---------------- binarize x -> bf16 +-1 (x >= 0.5) ------------------------
__global__ void bp_binx(const float* __restrict__ x) {
    size_t i = ((size_t)blockIdx.x * blockDim.x + threadIdx.x) * 4;
    float4 v = *(const float4*)&x[i];
    uint32_t p = 0x3F80u, n = 0xBF80u;
    uint2 o;
    o.x = (v.x >= 0.5f ? p : n) | ((v.y >= 0.5f ? p : n) << 16);
    o.y = (v.z >= 0.5f ? p : n) | ((v.w >= 0.5f ? p : n) << 16);
    *(uint2*)&g_A[0][i] = o;
}

// ---------------- binarize + transpose W -> bf16 +-1 [N][K] ----------------
__global__ void bp_binw(const float* __restrict__ W, int which, int N) {
    __shared__ float tile[32][33];
    int j0 = blockIdx.x * 32, k0 = blockIdx.y * 32;
    tile[threadIdx.y][threadIdx.x] = W[(size_t)(k0 + threadIdx.y) * N + j0 + threadIdx.x];
    __syncthreads();
    float v = tile[threadIdx.x][threadIdx.y];   // element (k0+tx, j0+ty)
    __nv_bfloat16* Wt = (which == 0) ? g_W0 : (which == 1) ? g_W1 : g_W2;
    *(uint16_t*)&Wt[(size_t)(j0 + threadIdx.y) * KBITS + k0 + threadIdx.x] =
        (v >= 0.f) ? 0x3F80u : 0xBF80u;
}

// ---------------- zero stats ----------------------------------------------
__global__ void bp_zero(int n) {
    int i = blockIdx.x * blockDim.x + threadIdx.x;
    if (i < n) { g_colsum[i] = 0; g_colsq[i] = 0ull; g_colmax[i] = (int)0x80000000; }
    if (i < N3) g_Z[i] = 0.f;
}

// ---------------- bf16 HMMA GEMM + fused column stats ----------------------
// C[BM=256, BN=128] = A[m0:, :] * B[n0:, :]^T, K=4096, all-+-1, exact in f32.
__global__ __launch_bounds__(512, 1) void bp_hmma(int asel, int wsel, int N, int l3) {
    extern __shared__ char smem[];
    uint32_t sbase = smem_u32(smem);
    int tid = threadIdx.x, wid = tid >> 5, lane = tid & 31;
    int grp = lane >> 2, tig = lane & 3;
    int wm = wid >> 2, wn = wid & 3;            // 4 x 4 warp grid -> warp tile 64x32
    int sel = lane >> 3, ilane = lane & 7;

    const __nv_bfloat16* A = g_A[asel];
    const __nv_bfloat16* B = (wsel == 0) ? g_W0 : (wsel == 1) ? g_W1 : g_W2;
    int m0 = blockIdx.y * BM, n0 = blockIdx.x * BN;
    const char* gA = (const char*)(A + (size_t)m0 * KBITS);
    const char* gB = (const char*)(B + (size_t)n0 * KBITS);

    // per-lane ldmatrix offsets (within a stage)
    uint32_t offA = (uint32_t)(wm * 64 + (sel & 1) * 8 + ilane) * 128;
    uint32_t c0a  = (uint32_t)(sel >> 1);
    uint32_t offB = (uint32_t)(wn * 32 + (sel >> 1) * 8 + ilane) * 128;
    uint32_t c0b  = (uint32_t)(sel & 1);

    float acc[4][4][4];
#pragma unroll
    for (int mi = 0; mi < 4; mi++)
#pragma unroll
        for (int ni = 0; ni < 4; ni++)
#pragma unroll
            for (int r = 0; r < 4; r++) acc[mi][ni][r] = 0.f;

    int lr = tid >> 3, lw = tid & 7;            // cp.async: row (0..63), 16B col
    auto load_stage = [&](int kt) {
        int st = kt & (NSTAGE - 1);
        uint32_t sA = sbase + st * A_STAGE;
        uint32_t sB = sbase + NSTAGE * A_STAGE + st * B_STAGE;
        size_t kb = (size_t)kt * 128;           // BK bf16 = 128 bytes
#pragma unroll
        for (int e = 0; e < 4; e++) {           // A: 256 rows
            int r = lr + e * 64;
            uint32_t sw = (uint32_t)((lw * 16) ^ ((r & 7) << 4));
            CP16(sA + r * 128 + sw, gA + (size_t)r * (KBITS * 2) + kb + lw * 16);
        }
#pragma unroll
        for (int e = 0; e < 2; e++) {           // B: 128 rows
            int r = lr + e * 64;
            uint32_t sw = (uint32_t)((lw * 16) ^ ((r & 7) << 4));
            CP16(sB + r * 128 + sw, gB + (size_t)r * (KBITS * 2) + kb + lw * 16);
        }
    };

#pragma unroll
    for (int kt = 0; kt < NSTAGE - 1; kt++) { load_stage(kt); CP_COMMIT(); }

    for (int kt = 0; kt < NKIT; kt++) {
        CP_WAIT2();
        __syncthreads();                        // single barrier per k-iter
        if (kt + NSTAGE - 1 < NKIT) load_stage(kt + NSTAGE - 1);
        CP_COMMIT();

        int st = kt & (NSTAGE - 1);
        uint32_t sA = sbase + st * A_STAGE;
        uint32_t sB = sbase + NSTAGE * A_STAGE + st * B_STAGE;
#pragma unroll
        for (int k16 = 0; k16 < 4; k16++) {
            uint32_t ca = ((c0a + 2 * k16) ^ (uint32_t)ilane) << 4;
            uint32_t cb = ((c0b + 2 * k16) ^ (uint32_t)ilane) << 4;
            uint32_t a[4][4], b[2][4];
#pragma unroll
            for (int mi = 0; mi < 4; mi++)
                LDSM_X4(a[mi], sA + offA + mi * 2048 + ca);
#pragma unroll
            for (int nb = 0; nb < 2; nb++)
                LDSM_X4(b[nb], sB + offB + nb * 2048 + cb);
#pragma unroll
            for (int mi = 0; mi < 4; mi++) {
                hmma(acc[mi][0], a[mi], b[0][0], b[0][1]);
                hmma(acc[mi][1], a[mi], b[0][2], b[0][3]);
                hmma(acc[mi][2], a[mi], b[1][0], b[1][1]);
                hmma(acc[mi][3], a[mi], b[1][2], b[1][3]);
            }
        }
        // NOTE: no trailing barrier. Next iteration's cp.async targets stage
        // (kt+NSTAGE-1) mod NSTAGE != kt, and the top barrier bounds warp skew
        // to one iteration, so in-flight reads of stage kt are never clobbered.
    }

    // ---------------- epilogue: write s (int16, row-major) + stats ---------
    int iv[4][4][4];
#pragma unroll
    for (int mi = 0; mi < 4; mi++)
#pragma unroll
        for (int ni = 0; ni < 4; ni++)
#pragma unroll
            for (int r = 0; r < 4; r++)
                iv[mi][ni][r] = __float2int_rn(acc[mi][ni][r]);

#pragma unroll
    for (int mi = 0; mi < 4; mi++) {
        int r0 = m0 + wm * 64 + mi * 16 + grp;
#pragma unroll
        for (int ni = 0; ni < 4; ni++) {
            int c0 = n0 + wn * 32 + ni * 8 + tig * 2;
            int* v = iv[mi][ni];
            *(uint32_t*)&g_s[(size_t)r0 * N + c0] =
                (uint32_t)(uint16_t)(int16_t)v[0] | ((uint32_t)(uint16_t)(int16_t)v[1] << 16);
            *(uint32_t*)&g_s[(size_t)(r0 + 8) * N + c0] =
                (uint32_t)(uint16_t)(int16_t)v[2] | ((uint32_t)(uint16_t)(int16_t)v[3] << 16);
        }
    }
#pragma unroll
    for (int ni = 0; ni < 4; ni++) {
        int s0 = 0, s1 = 0, q0 = 0, q1 = 0, x0 = (int)0x80000000, x1 = (int)0x80000000;
#pragma unroll
        for (int mi = 0; mi < 4; mi++) {
            int* v = iv[mi][ni];
            s0 += v[0] + v[2];           s1 += v[1] + v[3];
            q0 += v[0]*v[0] + v[2]*v[2]; q1 += v[1]*v[1] + v[3]*v[3];
            x0 = max(x0, max(v[0], v[2])); x1 = max(x1, max(v[1], v[3]));
        }
        s0 = wsum8(s0); s1 = wsum8(s1);
        q0 = wsum8(q0); q1 = wsum8(q1);
        if (l3) { x0 = wmax8(x0); x1 = wmax8(x1); }
        if (grp == 0) {
            int col = n0 + wn * 32 + ni * 8 + tig * 2;
            atomicAdd(&g_colsum[col],     s0);
            atomicAdd(&g_colsum[col + 1], s1);
            atomicAdd(&g_colsq[col],     (unsigned long long)(long long)q0);
            atomicAdd(&g_colsq[col + 1], (unsigned long long)(long long)q1);
            if (l3) {
                atomicMax(&g_colmax[col],     x0);
                atomicMax(&g_colmax[col + 1], x1);
            }
        }
    }
}

// ---------------- per-column rg = gamma * rsqrt(var+eps) -------------------
__global__ void bp_colprep(int N, const float* __restrict__ gamma, int layer) {
    int j = blockIdx.x * blockDim.x + threadIdx.x;
    if (j < N) {
        double mu  = (double)g_colsum[j] / (double)BATCH;
        double var = (double)g_colsq[j] / (double)BATCH - mu * mu;
        g_rg[j] = (float)((double)gamma[layer] / sqrt(var + BN_EPS));
    }
}

// ---------------- binarize normalized activations -> bf16 +-1 --------------
// sign((s*B - colsum)*rg + beta*B); exact for beta = 0.
__global__ void bp_bins(int N, int dst, const float* __restrict__ beta, int layer) {
    size_t i = ((size_t)blockIdx.x * blockDim.x + threadIdx.x) * 8;
    int col0 = (int)(i & (size_t)(N - 1));
    uint4 sp = *(const uint4*)&g_s[i];
    int sv[8];
    sv[0] = (int)(int16_t)(sp.x & 0xFFFF); sv[1] = (int)(int16_t)(sp.x >> 16);
    sv[2] = (int)(int16_t)(sp.y & 0xFFFF); sv[3] = (int)(int16_t)(sp.y >> 16);
    sv[4] = (int)(int16_t)(sp.z & 0xFFFF); sv[5] = (int)(int16_t)(sp.z >> 16);
    sv[6] = (int)(int16_t)(sp.w & 0xFFFF); sv[7] = (int)(int16_t)(sp.w >> 16);
    float b = beta[layer] * (float)BATCH;
    uint32_t h[8];
#pragma unroll
    for (int e = 0; e < 8; e++) {
        int num = sv[e] * BATCH - g_colsum[col0 + e];
        float v = (float)num * g_rg[col0 + e] + b;
        h[e] = (v >= 0.f) ? 0x3F80u : 0xBF80u;
    }
    uint4 o;
    o.x = h[0] | (h[1] << 16); o.y = h[2] | (h[3] << 16);
    o.z = h[4] | (h[5] << 16); o.w = h[6] | (h[7] << 16);
    *(uint4*)&g_A[dst][i] = o;
}

// ---------------- softmax partial sums (s row-major) -----------------------
__global__ void bp_softz() {                    // grid 256, block 256
    int r0 = blockIdx.x * 32;
    int t = threadIdx.x;
    float rg[4], acc[4];
    int   mx[4];
#pragma unroll
    for (int q = 0; q < 4; q++) {
        rg[q]  = g_rg[t + q * 256];
        mx[q]  = g_colmax[t + q * 256];
        acc[q] = 0.f;
    }
    for (int r = r0; r < r0 + 32; r++) {
        const int16_t* row = &g_s[(size_t)r * N3];
#pragma unroll
        for (int q = 0; q < 4; q++)
            acc[q] += expf(rg[q] * (float)(row[t + q * 256] - mx[q]));
    }
#pragma unroll
    for (int q = 0; q < 4; q++) atomicAdd(&g_Z[t + q * 256], acc[q]);
}

__global__ void bp_invz() {
    int j = blockIdx.x * blockDim.x + threadIdx.x;
    if (j < N3) g_invZ[j] = 1.f / g_Z[j];
}

// ---------------- writeout (row-major, fully coalesced) --------------------
__global__ void bp_writeout(float* __restrict__ out) {
    size_t e = (size_t)blockIdx.x * blockDim.x + threadIdx.x;
    int j = (int)(e & (N3 - 1));
    out[e] = expf(g_rg[j] * (float)(g_s[e] - g_colmax[j])) * g_invZ[j];
}

// ---------------- launch ---------------------------------------------------
extern "C" void kernel_launch(void* const* d_in, const int* in_sizes, int n_in,
                              void* d_out, int out_size) {
    const float* x     = (const float*)d_in[0];
    const float* W0    = (const float*)d_in[1];
    const float* W1    = (const float*)d_in[2];
    const float* W2    = (const float*)d_in[3];
    const float* gamma = (const float*)d_in[4];
    const float* beta  = (const float*)d_in[5];
    float* out = (float*)d_out;

    cudaFuncSetAttribute(bp_hmma, cudaFuncAttributeMaxDynamicSharedMemorySize, SMEM_TOTAL);

    dim3 b32(32, 32);
    bp_binx<<<(BATCH * KBITS / 4) / 256, 256>>>(x);
    bp_binw<<<dim3(N12 / 32, KBITS / 32), b32>>>(W0, 0, N12);
    bp_binw<<<dim3(N12 / 32, KBITS / 32), b32>>>(W1, 1, N12);
    bp_binw<<<dim3(N3  / 32, KBITS / 32), b32>>>(W2, 2, N3);

    // ---- layer 0 ----
    bp_zero<<<N12 / 256, 256>>>(N12);
    bp_hmma<<<dim3(N12 / BN, BATCH / BM), 512, SMEM_TOTAL>>>(0, 0, N12, 0);
    bp_colprep<<<N12 / 256, 256>>>(N12, gamma, 0);
    bp_bins<<<(BATCH * N12 / 8) / 256, 256>>>(N12, 1, beta, 0);

    // ---- layer 1 ----
    bp_zero<<<N12 / 256, 256>>>(N12);
    bp_hmma<<<dim3(N12 / BN, BATCH / BM), 512, SMEM_TOTAL>>>(1, 1, N12, 0);
    bp_colprep<<<N12 / 256, 256>>>(N12, gamma, 1);
    bp_bins<<<(BATCH * N12 / 8) / 256, 256>>>(N12, 0, beta, 1);

    // ---- layer 2 (row-major s, +colmax) ----
    bp_zero<<<N12 / 256, 256>>>(N12);
    bp_hmma<<<dim3(N3 / BN, BATCH / BM), 512, SMEM_TOTAL>>>(0, 2, N3, 1);
    bp_colprep<<<N3 / 256, 256>>>(N3, gamma, 2);
    bp_softz<<<256, 256>>>();
    bp_invz<<<N3 / 256, 256>>>();
    bp_writeout<<<(BATCH * N3) / 256, 256>>>(out);
}

// round 10
// speedup vs baseline: 2.5483x; 1.0468x over previous
#include <cuda_runtime.h>
#include <cuda_bf16.h>
#include <cstdint>

#define BATCH   8192
#define KBITS   4096
#define N12     4096
#define N3      1024
#define BN_EPS  1e-5

// GEMM tiling: 2 CTAs per SM, 256 threads each
#define BM      128
#define BN      128
#define BK      64                  // K elems (bf16) per stage = 128 B rows
#define NKIT    (KBITS / BK)        // 64 k-iterations
#define NSTAGE  3
#define A_STAGE (BM * 128)          // 16384 B
#define B_STAGE (BN * 128)          // 16384 B
#define SMEM_TOTAL (NSTAGE * (A_STAGE + B_STAGE))   // 98304 -> 2 CTAs/SM

// ---------------- device globals (no allocation allowed) -------------------
__device__ __nv_bfloat16 g_A[2][(size_t)BATCH * KBITS];   // ping-pong activations (2 x 64MB)
__device__ __nv_bfloat16 g_W0[(size_t)N12 * KBITS];       // [N][K] bf16 (32MB)
__device__ __nv_bfloat16 g_W1[(size_t)N12 * KBITS];
__device__ __nv_bfloat16 g_W2[(size_t)N3  * KBITS];       // 8MB
__device__ int16_t g_s[(size_t)BATCH * N12];              // 64MB, row-major always
__device__ int                 g_colsum[N12];
__device__ unsigned long long  g_colsq[N12];
__device__ int                 g_colmax[N12];
__device__ float               g_rg[N12];
__device__ float               g_Z[N3];
__device__ float               g_invZ[N3];

// ---------------- PTX helpers ---------------------------------------------
#define CP16(dst, src) \
    asm volatile("cp.async.cg.shared.global [%0], [%1], 16;" :: "r"(dst), "l"(src) : "memory")
#define CP_COMMIT() asm volatile("cp.async.commit_group;" ::: "memory")
#define CP_WAIT1()  asm volatile("cp.async.wait_group 1;" ::: "memory")

__device__ __forceinline__ uint32_t smem_u32(const void* p) {
    uint32_t a;
    asm("{ .reg .u64 t; cvta.to.shared.u64 t, %1; cvt.u32.u64 %0, t; }"
        : "=r"(a) : "l"(p));
    return a;
}

#define LDSM_X4(r, addr) \
    asm volatile("ldmatrix.sync.aligned.m8n8.x4.shared.b16 {%0,%1,%2,%3}, [%4];" \
        : "=r"((r)[0]), "=r"((r)[1]), "=r"((r)[2]), "=r"((r)[3]) : "r"(addr))

__device__ __forceinline__ void hmma(float* c, const uint32_t* a,
                                     uint32_t b0, uint32_t b1) {
    asm volatile(
        "mma.sync.aligned.m16n8k16.row.col.f32.bf16.bf16.f32 "
        "{%0,%1,%2,%3}, {%4,%5,%6,%7}, {%8,%9}, {%0,%1,%2,%3};"
        : "+f"(c[0]), "+f"(c[1]), "+f"(c[2]), "+f"(c[3])
        : "r"(a[0]), "r"(a[1]), "r"(a[2]), "r"(a[3]), "r"(b0), "r"(b1));
}

__device__ __forceinline__ int wsum8(int v) {
    v += __shfl_xor_sync(0xFFFFFFFFu, v, 4);
    v += __shfl_xor_sync(0xFFFFFFFFu, v, 8);
    v += __shfl_xor_sync(0xFFFFFFFFu, v, 16);
    return v;
}
__device__ __forceinline__ int wmax8(int v) {
    v = max(v, __shfl_xor_sync(0xFFFFFFFFu, v, 4));
    v = max(v, __shfl_xor_sync(0xFFFFFFFFu, v, 8));
    v = max(v, __shfl_xor_sync(0xFFFFFFFFu, v, 16));
    return v;
}

// ---------------- binarize x -> bf16 +-1 (x >= 0.5) ------------------------
__global__ void bp_binx(const float* __restrict__ x) {
    size_t i = ((size_t)blockIdx.x * blockDim.x + threadIdx.x) * 4;
    float4 v = *(const float4*)&x[i];
    uint32_t p = 0x3F80u, n = 0xBF80u;
    uint2 o;
    o.x = (v.x >= 0.5f ? p : n) | ((v.y >= 0.5f ? p : n) << 16);
    o.y = (v.z >= 0.5f ? p : n) | ((v.w >= 0.5f ? p : n) << 16);
    *(uint2*)&g_A[0][i] = o;
}

// ---------------- binarize + transpose W -> bf16 +-1 [N][K] ----------------
__global__ void bp_binw(const float* __restrict__ W, int which, int N) {
    __shared__ float tile[32][33];
    int j0 = blockIdx.x * 32, k0 = blockIdx.y * 32;
    tile[threadIdx.y][threadIdx.x] = W[(size_t)(k0 + threadIdx.y) * N + j0 + threadIdx.x];
    __syncthreads();
    float v = tile[threadIdx.x][threadIdx.y];   // element (k0+tx, j0+ty)
    __nv_bfloat16* Wt = (which == 0) ? g_W0 : (which == 1) ? g_W1 : g_W2;
    *(uint16_t*)&Wt[(size_t)(j0 + threadIdx.y) * KBITS + k0 + threadIdx.x] =
        (v >= 0.f) ? 0x3F80u : 0xBF80u;
}

// ---------------- zero stats ----------------------------------------------
__global__ void bp_zero(int n) {
    int i = blockIdx.x * blockDim.x + threadIdx.x;
    if (i < n) { g_colsum[i] = 0; g_colsq[i] = 0ull; g_colmax[i] = (int)0x80000000; }
    if (i < N3) g_Z[i] = 0.f;
}

// ---------------- bf16 HMMA GEMM + fused column stats ----------------------
// C[BM=128, BN=128] = A[m0:, :] * B[n0:, :]^T, K=4096, all-+-1, exact in f32.
__global__ __launch_bounds__(256, 2) void bp_hmma(int asel, int wsel, int N, int l3) {
    extern __shared__ char smem[];
    uint32_t sbase = smem_u32(smem);
    int tid = threadIdx.x, wid = tid >> 5, lane = tid & 31;
    int grp = lane >> 2, tig = lane & 3;
    int wm = wid >> 2, wn = wid & 3;            // 2 x 4 warp grid -> warp tile 64x32
    int sel = lane >> 3, ilane = lane & 7;

    const __nv_bfloat16* A = g_A[asel];
    const __nv_bfloat16* B = (wsel == 0) ? g_W0 : (wsel == 1) ? g_W1 : g_W2;
    int m0 = blockIdx.y * BM, n0 = blockIdx.x * BN;
    const char* gA = (const char*)(A + (size_t)m0 * KBITS);
    const char* gB = (const char*)(B + (size_t)n0 * KBITS);

    // per-lane ldmatrix offsets (within a stage)
    uint32_t offA = (uint32_t)(wm * 64 + (sel & 1) * 8 + ilane) * 128;
    uint32_t c0a  = (uint32_t)(sel >> 1);
    uint32_t offB = (uint32_t)(wn * 32 + (sel >> 1) * 8 + ilane) * 128;
    uint32_t c0b  = (uint32_t)(sel & 1);

    float acc[4][4][4];
#pragma unroll
    for (int mi = 0; mi < 4; mi++)
#pragma unroll
        for (int ni = 0; ni < 4; ni++)
#pragma unroll
            for (int r = 0; r < 4; r++) acc[mi][ni][r] = 0.f;

    int lr = tid >> 3, lw = tid & 7;            // cp.async: row (0..31), 16B col
    auto load_stage = [&](int kt) {
        int st = kt % NSTAGE;
        uint32_t sA = sbase + st * A_STAGE;
        uint32_t sB = sbase + NSTAGE * A_STAGE + st * B_STAGE;
        size_t kb = (size_t)kt * 128;           // BK bf16 = 128 bytes
#pragma unroll
        for (int e = 0; e < 4; e++) {           // A: 128 rows
            int r = lr + e * 32;
            uint32_t sw = (uint32_t)((lw * 16) ^ ((r & 7) << 4));
            CP16(sA + r * 128 + sw, gA + (size_t)r * (KBITS * 2) + kb + lw * 16);
        }
#pragma unroll
        for (int e = 0; e < 4; e++) {           // B: 128 rows
            int r = lr + e * 32;
            uint32_t sw = (uint32_t)((lw * 16) ^ ((r & 7) << 4));
            CP16(sB + r * 128 + sw, gB + (size_t)r * (KBITS * 2) + kb + lw * 16);
        }
    };

#pragma unroll
    for (int kt = 0; kt < NSTAGE - 1; kt++) { load_stage(kt); CP_COMMIT(); }

    for (int kt = 0; kt < NKIT; kt++) {
        CP_WAIT1();
        __syncthreads();                        // single barrier per k-iter
        if (kt + NSTAGE - 1 < NKIT) load_stage(kt + NSTAGE - 1);
        CP_COMMIT();

        int st = kt % NSTAGE;
        uint32_t sA = sbase + st * A_STAGE;
        uint32_t sB = sbase + NSTAGE * A_STAGE + st * B_STAGE;
#pragma unroll
        for (int k16 = 0; k16 < 4; k16++) {
            uint32_t ca = ((c0a + 2 * k16) ^ (uint32_t)ilane) << 4;
            uint32_t cb = ((c0b + 2 * k16) ^ (uint32_t)ilane) << 4;
            uint32_t a[4][4], b[2][4];
#pragma unroll
            for (int mi = 0; mi < 4; mi++)
                LDSM_X4(a[mi], sA + offA + mi * 2048 + ca);
#pragma unroll
            for (int nb = 0; nb < 2; nb++)
                LDSM_X4(b[nb], sB + offB + nb * 2048 + cb);
#pragma unroll
            for (int mi = 0; mi < 4; mi++) {
                hmma(acc[mi][0], a[mi], b[0][0], b[0][1]);
                hmma(acc[mi][1], a[mi], b[0][2], b[0][3]);
                hmma(acc[mi][2], a[mi], b[1][0], b[1][1]);
                hmma(acc[mi][3], a[mi], b[1][2], b[1][3]);
            }
        }
        // No trailing barrier: with NSTAGE=3, iter kt writes stage (kt+2)%3 ==
        // stage read at iter kt-1, and the top barrier of iter kt orders all
        // iter kt-1 reads before any iter-kt cp.async issue.
    }

    // ---------------- epilogue: write s (int16, row-major) + stats ---------
    int iv[4][4][4];
#pragma unroll
    for (int mi = 0; mi < 4; mi++)
#pragma unroll
        for (int ni = 0; ni < 4; ni++)
#pragma unroll
            for (int r = 0; r < 4; r++)
                iv[mi][ni][r] = __float2int_rn(acc[mi][ni][r]);

#pragma unroll
    for (int mi = 0; mi < 4; mi++) {
        int r0 = m0 + wm * 64 + mi * 16 + grp;
#pragma unroll
        for (int ni = 0; ni < 4; ni++) {
            int c0 = n0 + wn * 32 + ni * 8 + tig * 2;
            int* v = iv[mi][ni];
            *(uint32_t*)&g_s[(size_t)r0 * N + c0] =
                (uint32_t)(uint16_t)(int16_t)v[0] | ((uint32_t)(uint16_t)(int16_t)v[1] << 16);
            *(uint32_t*)&g_s[(size_t)(r0 + 8) * N + c0] =
                (uint32_t)(uint16_t)(int16_t)v[2] | ((uint32_t)(uint16_t)(int16_t)v[3] << 16);
        }
    }
#pragma unroll
    for (int ni = 0; ni < 4; ni++) {
        int s0 = 0, s1 = 0, q0 = 0, q1 = 0, x0 = (int)0x80000000, x1 = (int)0x80000000;
#pragma unroll
        for (int mi = 0; mi < 4; mi++) {
            int* v = iv[mi][ni];
            s0 += v[0] + v[2];           s1 += v[1] + v[3];
            q0 += v[0]*v[0] + v[2]*v[2]; q1 += v[1]*v[1] + v[3]*v[3];
            x0 = max(x0, max(v[0], v[2])); x1 = max(x1, max(v[1], v[3]));
        }
        s0 = wsum8(s0); s1 = wsum8(s1);
        q0 = wsum8(q0); q1 = wsum8(q1);
        if (l3) { x0 = wmax8(x0); x1 = wmax8(x1); }
        if (grp == 0) {
            int col = n0 + wn * 32 + ni * 8 + tig * 2;
            atomicAdd(&g_colsum[col],     s0);
            atomicAdd(&g_colsum[col + 1], s1);
            atomicAdd(&g_colsq[col],     (unsigned long long)(long long)q0);
            atomicAdd(&g_colsq[col + 1], (unsigned long long)(long long)q1);
            if (l3) {
                atomicMax(&g_colmax[col],     x0);
                atomicMax(&g_colmax[col + 1], x1);
            }
        }
    }
}

// ---------------- per-column rg = gamma * rsqrt(var+eps) -------------------
__global__ void bp_colprep(int N, const float* __restrict__ gamma, int layer) {
    int j = blockIdx.x * blockDim.x + threadIdx.x;
    if (j < N) {
        double mu  = (double)g_colsum[j] / (double)BATCH;
        double var = (double)g_colsq[j] / (double)BATCH - mu * mu;
        g_rg[j] = (float)((double)gamma[layer] / sqrt(var + BN_EPS));
    }
}

// ---------------- binarize normalized activations -> bf16 +-1 --------------
// sign((s*B - colsum)*rg + beta*B); exact for beta = 0.
__global__ void bp_bins(int N, int dst, const float* __restrict__ beta, int layer) {
    size_t i = ((size_t)blockIdx.x * blockDim.x + threadIdx.x) * 8;
    int col0 = (int)(i & (size_t)(N - 1));
    uint4 sp = *(const uint4*)&g_s[i];
    int sv[8];
    sv[0] = (int)(int16_t)(sp.x & 0xFFFF); sv[1] = (int)(int16_t)(sp.x >> 16);
    sv[2] = (int)(int16_t)(sp.y & 0xFFFF); sv[3] = (int)(int16_t)(sp.y >> 16);
    sv[4] = (int)(int16_t)(sp.z & 0xFFFF); sv[5] = (int)(int16_t)(sp.z >> 16);
    sv[6] = (int)(int16_t)(sp.w & 0xFFFF); sv[7] = (int)(int16_t)(sp.w >> 16);
    float b = beta[layer] * (float)BATCH;
    uint32_t h[8];
#pragma unroll
    for (int e = 0; e < 8; e++) {
        int num = sv[e] * BATCH - g_colsum[col0 + e];
        float v = (float)num * g_rg[col0 + e] + b;
        h[e] = (v >= 0.f) ? 0x3F80u : 0xBF80u;
    }
    uint4 o;
    o.x = h[0] | (h[1] << 16); o.y = h[2] | (h[3] << 16);
    o.z = h[4] | (h[5] << 16); o.w = h[6] | (h[7] << 16);
    *(uint4*)&g_A[dst][i] = o;
}

// ---------------- softmax partial sums (s row-major) -----------------------
__global__ void bp_softz() {                    // grid 256, block 256
    int r0 = blockIdx.x * 32;
    int t = threadIdx.x;
    float rg[4], acc[4];
    int   mx[4];
#pragma unroll
    for (int q = 0; q < 4; q++) {
        rg[q]  = g_rg[t + q * 256];
        mx[q]  = g_colmax[t + q * 256];
        acc[q] = 0.f;
    }
    for (int r = r0; r < r0 + 32; r++) {
        const int16_t* row = &g_s[(size_t)r * N3];
#pragma unroll
        for (int q = 0; q < 4; q++)
            acc[q] += expf(rg[q] * (float)(row[t + q * 256] - mx[q]));
    }
#pragma unroll
    for (int q = 0; q < 4; q++) atomicAdd(&g_Z[t + q * 256], acc[q]);
}

__global__ void bp_invz() {
    int j = blockIdx.x * blockDim.x + threadIdx.x;
    if (j < N3) g_invZ[j] = 1.f / g_Z[j];
}

// ---------------- writeout (row-major, fully coalesced) --------------------
__global__ void bp_writeout(float* __restrict__ out) {
    size_t e = (size_t)blockIdx.x * blockDim.x + threadIdx.x;
    int j = (int)(e & (N3 - 1));
    out[e] = expf(g_rg[j] * (float)(g_s[e] - g_colmax[j])) * g_invZ[j];
}

// ---------------- launch ---------------------------------------------------
extern "C" void kernel_launch(void* const* d_in, const int* in_sizes, int n_in,
                              void* d_out, int out_size) {
    const float* x     = (const float*)d_in[0];
    const float* W0    = (const float*)d_in[1];
    const float* W1    = (const float*)d_in[2];
    const float* W2    = (const float*)d_in[3];
    const float* gamma = (const float*)d_in[4];
    const float* beta  = (const float*)d_in[5];
    float* out = (float*)d_out;

    cudaFuncSetAttribute(bp_hmma, cudaFuncAttributeMaxDynamicSharedMemorySize, SMEM_TOTAL);

    dim3 b32(32, 32);
    bp_binx<<<(BATCH * KBITS / 4) / 256, 256>>>(x);
    bp_binw<<<dim3(N12 / 32, KBITS / 32), b32>>>(W0, 0, N12);
    bp_binw<<<dim3(N12 / 32, KBITS / 32), b32>>>(W1, 1, N12);
    bp_binw<<<dim3(N3  / 32, KBITS / 32), b32>>>(W2, 2, N3);

    // ---- layer 0 ----
    bp_zero<<<N12 / 256, 256>>>(N12);
    bp_hmma<<<dim3(N12 / BN, BATCH / BM), 256, SMEM_TOTAL>>>(0, 0, N12, 0);
    bp_colprep<<<N12 / 256, 256>>>(N12, gamma, 0);
    bp_bins<<<(BATCH * N12 / 8) / 256, 256>>>(N12, 1, beta, 0);

    // ---- layer 1 ----
    bp_zero<<<N12 / 256, 256>>>(N12);
    bp_hmma<<<dim3(N12 / BN, BATCH / BM), 256, SMEM_TOTAL>>>(1, 1, N12, 0);
    bp_colprep<<<N12 / 256, 256>>>(N12, gamma, 1);
    bp_bins<<<(BATCH * N12 / 8) / 256, 256>>>(N12, 0, beta, 1);

    // ---- layer 2 (row-major s, +colmax) ----
    bp_zero<<<N12 / 256, 256>>>(N12);
    bp_hmma<<<dim3(N3 / BN, BATCH / BM), 256, SMEM_TOTAL>>>(0, 2, N3, 1);
    bp_colprep<<<N3 / 256, 256>>>(N3, gamma, 2);
    bp_softz<<<256, 256>>>();
    bp_invz<<<N3 / 256, 256>>>();
    bp_writeout<<<(BATCH * N3) / 256, 256>>>(out);
}

// round 13
// speedup vs baseline: 2.8284x; 1.1099x over previous
#include <cuda_runtime.h>
#include <cuda_bf16.h>
#include <cstdint>

#define BATCH   8192
#define KBITS   4096
#define N12     4096
#define N3      1024
#define BN_EPS  1e-5

// GEMM tiling: 2 CTAs per SM, 256 threads each
#define BM      128
#define BN      128
#define BK      64                  // K elems (bf16) per stage = 128 B rows
#define NKIT    (KBITS / BK)        // 64 k-iterations
#define NSTAGE  3
#define A_STAGE (BM * 128)          // 16384 B
#define B_STAGE (BN * 128)          // 16384 B
#define SMEM_TOTAL (NSTAGE * (A_STAGE + B_STAGE))   // 98304 -> 2 CTAs/SM

// ---------------- device globals (no allocation allowed) -------------------
__device__ __nv_bfloat16 g_A[2][(size_t)BATCH * KBITS];   // ping-pong activations (2 x 64MB)
__device__ __nv_bfloat16 g_W0[(size_t)N12 * KBITS];       // [N][K] bf16 (32MB)
__device__ __nv_bfloat16 g_W1[(size_t)N12 * KBITS];
__device__ __nv_bfloat16 g_W2[(size_t)N3  * KBITS];       // 8MB
__device__ int16_t g_s[(size_t)BATCH * N12];              // 64MB, row-major always
__device__ int                 g_colsum[N12];
__device__ unsigned long long  g_colsq[N12];
__device__ int                 g_colmax[N12];
__device__ float               g_rg[N12];
__device__ float               g_Z[N3];
__device__ float               g_invZ[N3];

// ---------------- PTX helpers ---------------------------------------------
#define CP16(dst, src) \
    asm volatile("cp.async.cg.shared.global [%0], [%1], 16;" :: "r"(dst), "l"(src) : "memory")
#define CP_COMMIT() asm volatile("cp.async.commit_group;" ::: "memory")
#define CP_WAIT1()  asm volatile("cp.async.wait_group 1;" ::: "memory")

__device__ __forceinline__ uint32_t smem_u32(const void* p) {
    uint32_t a;
    asm("{ .reg .u64 t; cvta.to.shared.u64 t, %1; cvt.u32.u64 %0, t; }"
        : "=r"(a) : "l"(p));
    return a;
}

#define LDSM_X4(r, addr) \
    asm volatile("ldmatrix.sync.aligned.m8n8.x4.shared.b16 {%0,%1,%2,%3}, [%4];" \
        : "=r"((r)[0]), "=r"((r)[1]), "=r"((r)[2]), "=r"((r)[3]) : "r"(addr))

__device__ __forceinline__ void hmma(float* c, const uint32_t* a,
                                     uint32_t b0, uint32_t b1) {
    asm volatile(
        "mma.sync.aligned.m16n8k16.row.col.f32.bf16.bf16.f32 "
        "{%0,%1,%2,%3}, {%4,%5,%6,%7}, {%8,%9}, {%0,%1,%2,%3};"
        : "+f"(c[0]), "+f"(c[1]), "+f"(c[2]), "+f"(c[3])
        : "r"(a[0]), "r"(a[1]), "r"(a[2]), "r"(a[3]), "r"(b0), "r"(b1));
}

__device__ __forceinline__ int wsum8(int v) {
    v += __shfl_xor_sync(0xFFFFFFFFu, v, 4);
    v += __shfl_xor_sync(0xFFFFFFFFu, v, 8);
    v += __shfl_xor_sync(0xFFFFFFFFu, v, 16);
    return v;
}
__device__ __forceinline__ int wmax8(int v) {
    v = max(v, __shfl_xor_sync(0xFFFFFFFFu, v, 4));
    v = max(v, __shfl_xor_sync(0xFFFFFFFFu, v, 8));
    v = max(v, __shfl_xor_sync(0xFFFFFFFFu, v, 16));
    return v;
}

// ---------------- binarize x -> bf16 +-1 (x >= 0.5) ------------------------
__global__ void bp_binx(const float* __restrict__ x) {
    size_t i = ((size_t)blockIdx.x * blockDim.x + threadIdx.x) * 4;
    float4 v = *(const float4*)&x[i];
    uint32_t p = 0x3F80u, n = 0xBF80u;
    uint2 o;
    o.x = (v.x >= 0.5f ? p : n) | ((v.y >= 0.5f ? p : n) << 16);
    o.y = (v.z >= 0.5f ? p : n) | ((v.w >= 0.5f ? p : n) << 16);
    *(uint2*)&g_A[0][i] = o;
}

// ---------------- binarize + transpose W -> bf16 +-1 [N][K] ----------------
__global__ void bp_binw(const float* __restrict__ W, int which, int N) {
    __shared__ float tile[32][33];
    int j0 = blockIdx.x * 32, k0 = blockIdx.y * 32;
    tile[threadIdx.y][threadIdx.x] = W[(size_t)(k0 + threadIdx.y) * N + j0 + threadIdx.x];
    __syncthreads();
    float v = tile[threadIdx.x][threadIdx.y];   // element (k0+tx, j0+ty)
    __nv_bfloat16* Wt = (which == 0) ? g_W0 : (which == 1) ? g_W1 : g_W2;
    *(uint16_t*)&Wt[(size_t)(j0 + threadIdx.y) * KBITS + k0 + threadIdx.x] =
        (v >= 0.f) ? 0x3F80u : 0xBF80u;
}

// ---------------- zero stats ----------------------------------------------
__global__ void bp_zero(int n) {
    int i = blockIdx.x * blockDim.x + threadIdx.x;
    if (i < n) { g_colsum[i] = 0; g_colsq[i] = 0ull; g_colmax[i] = (int)0x80000000; }
    if (i < N3) g_Z[i] = 0.f;
}

// ---------------- bf16 HMMA GEMM + fused column stats ----------------------
// C[BM=128, BN=128] = A[m0:, :] * B[n0:, :]^T, K=4096, all-+-1, exact in f32.
__global__ __launch_bounds__(256, 2) void bp_hmma(int asel, int wsel, int N, int l3) {
    extern __shared__ char smem[];
    uint32_t sbase = smem_u32(smem);
    int tid = threadIdx.x, wid = tid >> 5, lane = tid & 31;
    int grp = lane >> 2, tig = lane & 3;
    int wm = wid >> 2, wn = wid & 3;            // 2 x 4 warp grid -> warp tile 64x32
    int sel = lane >> 3, ilane = lane & 7;

    const __nv_bfloat16* A = g_A[asel];
    const __nv_bfloat16* B = (wsel == 0) ? g_W0 : (wsel == 1) ? g_W1 : g_W2;
    int m0 = blockIdx.y * BM, n0 = blockIdx.x * BN;

    int lr = tid >> 3, lw = tid & 7;            // cp.async: row (0..31), 16B col
    // per-thread gmem bases, advanced by +128 bytes each k-iter
    const char* pA = (const char*)(A + (size_t)(m0 + lr) * KBITS) + lw * 16;
    const char* pB = (const char*)(B + (size_t)(n0 + lr) * KBITS) + lw * 16;
    // SMEM dest offset for row lr: row base + swizzled 16B column  (FIX: +lr*128)
    const uint32_t swz = (uint32_t)(lr * 128 + ((lw * 16) ^ ((lr & 7) << 4)));

    // per-lane ldmatrix offsets (within a stage)
    uint32_t offA = (uint32_t)(wm * 64 + (sel & 1) * 8 + ilane) * 128;
    uint32_t c0a  = (uint32_t)(sel >> 1);
    uint32_t offB = (uint32_t)(wn * 32 + (sel >> 1) * 8 + ilane) * 128;
    uint32_t c0b  = (uint32_t)(sel & 1);

    float acc[4][4][4];
#pragma unroll
    for (int mi = 0; mi < 4; mi++)
#pragma unroll
        for (int ni = 0; ni < 4; ni++)
#pragma unroll
            for (int r = 0; r < 4; r++) acc[mi][ni][r] = 0.f;

    // stage base addresses (rotated by MOVs, no per-iter multiplies)
    uint32_t sA0 = sbase,               sA1 = sA0 + A_STAGE, sA2 = sA1 + A_STAGE;
    uint32_t sB0 = sbase + 3 * A_STAGE, sB1 = sB0 + B_STAGE, sB2 = sB1 + B_STAGE;

    auto issue_cp = [&](uint32_t dA, uint32_t dB) {
#pragma unroll
        for (int e = 0; e < 4; e++) {           // A: 128 rows (32 per e-step)
            CP16(dA + (e * 32) * 128 + swz, pA + (size_t)(e * 32) * (KBITS * 2));
        }
#pragma unroll
        for (int e = 0; e < 4; e++) {           // B: 128 rows
            CP16(dB + (e * 32) * 128 + swz, pB + (size_t)(e * 32) * (KBITS * 2));
        }
        pA += 128; pB += 128;
        CP_COMMIT();
    };

    // prologue: stages 0,1
    issue_cp(sA0, sB0);
    issue_cp(sA1, sB1);

    for (int kt = 0; kt < NKIT; kt++) {
        CP_WAIT1();
        __syncthreads();                        // single barrier per k-iter

        // ---- start compute immediately: k16=0 fragments first -------------
        uint32_t a[4][4], b[2][4];
        {
            uint32_t ca = (c0a ^ (uint32_t)ilane) << 4;
            uint32_t cb = (c0b ^ (uint32_t)ilane) << 4;
#pragma unroll
            for (int mi = 0; mi < 4; mi++)
                LDSM_X4(a[mi], sA0 + offA + mi * 2048 + ca);
#pragma unroll
            for (int nb = 0; nb < 2; nb++)
                LDSM_X4(b[nb], sB0 + offB + nb * 2048 + cb);
        }

        // ---- then issue next stage's cp.async (writes stage kt+2 mod 3) ---
        if (kt + 2 < NKIT) issue_cp(sA2, sB2);
        else CP_COMMIT();                       // keep group count consistent

        // ---- k16=0 compute -------------------------------------------------
#pragma unroll
        for (int mi = 0; mi < 4; mi++) {
            hmma(acc[mi][0], a[mi], b[0][0], b[0][1]);
            hmma(acc[mi][1], a[mi], b[0][2], b[0][3]);
            hmma(acc[mi][2], a[mi], b[1][0], b[1][1]);
            hmma(acc[mi][3], a[mi], b[1][2], b[1][3]);
        }

        // ---- k16 = 1..3 ----------------------------------------------------
#pragma unroll
        for (int k16 = 1; k16 < 4; k16++) {
            uint32_t ca = ((c0a + 2 * k16) ^ (uint32_t)ilane) << 4;
            uint32_t cb = ((c0b + 2 * k16) ^ (uint32_t)ilane) << 4;
#pragma unroll
            for (int mi = 0; mi < 4; mi++)
                LDSM_X4(a[mi], sA0 + offA + mi * 2048 + ca);
#pragma unroll
            for (int nb = 0; nb < 2; nb++)
                LDSM_X4(b[nb], sB0 + offB + nb * 2048 + cb);
#pragma unroll
            for (int mi = 0; mi < 4; mi++) {
                hmma(acc[mi][0], a[mi], b[0][0], b[0][1]);
                hmma(acc[mi][1], a[mi], b[0][2], b[0][3]);
                hmma(acc[mi][2], a[mi], b[1][0], b[1][1]);
                hmma(acc[mi][3], a[mi], b[1][2], b[1][3]);
            }
        }

        // rotate stage pointers: compute stage advances, freed stage becomes fill target
        uint32_t tA = sA0; sA0 = sA1; sA1 = sA2; sA2 = tA;
        uint32_t tB = sB0; sB0 = sB1; sB1 = sB2; sB2 = tB;
        // No trailing barrier: iter kt writes the stage read at iter kt-1; the
        // top barrier of iter kt orders those reads before this iter's cp.async.
    }

    // ---------------- epilogue: write s (int16, row-major) + stats ---------
    int iv[4][4][4];
#pragma unroll
    for (int mi = 0; mi < 4; mi++)
#pragma unroll
        for (int ni = 0; ni < 4; ni++)
#pragma unroll
            for (int r = 0; r < 4; r++)
                iv[mi][ni][r] = __float2int_rn(acc[mi][ni][r]);

#pragma unroll
    for (int mi = 0; mi < 4; mi++) {
        int r0 = m0 + wm * 64 + mi * 16 + grp;
#pragma unroll
        for (int ni = 0; ni < 4; ni++) {
            int c0 = n0 + wn * 32 + ni * 8 + tig * 2;
            int* v = iv[mi][ni];
            *(uint32_t*)&g_s[(size_t)r0 * N + c0] =
                (uint32_t)(uint16_t)(int16_t)v[0] | ((uint32_t)(uint16_t)(int16_t)v[1] << 16);
            *(uint32_t*)&g_s[(size_t)(r0 + 8) * N + c0] =
                (uint32_t)(uint16_t)(int16_t)v[2] | ((uint32_t)(uint16_t)(int16_t)v[3] << 16);
        }
    }
#pragma unroll
    for (int ni = 0; ni < 4; ni++) {
        int s0 = 0, s1 = 0, q0 = 0, q1 = 0, x0 = (int)0x80000000, x1 = (int)0x80000000;
#pragma unroll
        for (int mi = 0; mi < 4; mi++) {
            int* v = iv[mi][ni];
            s0 += v[0] + v[2];           s1 += v[1] + v[3];
            q0 += v[0]*v[0] + v[2]*v[2]; q1 += v[1]*v[1] + v[3]*v[3];
            x0 = max(x0, max(v[0], v[2])); x1 = max(x1, max(v[1], v[3]));
        }
        s0 = wsum8(s0); s1 = wsum8(s1);
        q0 = wsum8(q0); q1 = wsum8(q1);
        if (l3) { x0 = wmax8(x0); x1 = wmax8(x1); }
        if (grp == 0) {
            int col = n0 + wn * 32 + ni * 8 + tig * 2;
            atomicAdd(&g_colsum[col],     s0);
            atomicAdd(&g_colsum[col + 1], s1);
            atomicAdd(&g_colsq[col],     (unsigned long long)(long long)q0);
            atomicAdd(&g_colsq[col + 1], (unsigned long long)(long long)q1);
            if (l3) {
                atomicMax(&g_colmax[col],     x0);
                atomicMax(&g_colmax[col + 1], x1);
            }
        }
    }
}

// ---------------- per-column rg = gamma * rsqrt(var+eps) -------------------
__global__ void bp_colprep(int N, const float* __restrict__ gamma, int layer) {
    int j = blockIdx.x * blockDim.x + threadIdx.x;
    if (j < N) {
        double mu  = (double)g_colsum[j] / (double)BATCH;
        double var = (double)g_colsq[j] / (double)BATCH - mu * mu;
        g_rg[j] = (float)((double)gamma[layer] / sqrt(var + BN_EPS));
    }
}

// ---------------- binarize normalized activations -> bf16 +-1 --------------
// sign((s*B - colsum)*rg + beta*B); exact for beta = 0.
__global__ void bp_bins(int N, int dst, const float* __restrict__ beta, int layer) {
    size_t i = ((size_t)blockIdx.x * blockDim.x + threadIdx.x) * 8;
    int col0 = (int)(i & (size_t)(N - 1));
    uint4 sp = *(const uint4*)&g_s[i];
    int sv[8];
    sv[0] = (int)(int16_t)(sp.x & 0xFFFF); sv[1] = (int)(int16_t)(sp.x >> 16);
    sv[2] = (int)(int16_t)(sp.y & 0xFFFF); sv[3] = (int)(int16_t)(sp.y >> 16);
    sv[4] = (int)(int16_t)(sp.z & 0xFFFF); sv[5] = (int)(int16_t)(sp.z >> 16);
    sv[6] = (int)(int16_t)(sp.w & 0xFFFF); sv[7] = (int)(int16_t)(sp.w >> 16);
    float b = beta[layer] * (float)BATCH;
    uint32_t h[8];
#pragma unroll
    for (int e = 0; e < 8; e++) {
        int num = sv[e] * BATCH - g_colsum[col0 + e];
        float v = (float)num * g_rg[col0 + e] + b;
        h[e] = (v >= 0.f) ? 0x3F80u : 0xBF80u;
    }
    uint4 o;
    o.x = h[0] | (h[1] << 16); o.y = h[2] | (h[3] << 16);
    o.z = h[4] | (h[5] << 16); o.w = h[6] | (h[7] << 16);
    *(uint4*)&g_A[dst][i] = o;
}

// ---------------- softmax partial sums (s row-major) -----------------------
__global__ void bp_softz() {                    // grid 256, block 256
    int r0 = blockIdx.x * 32;
    int t = threadIdx.x;
    float rg[4], acc[4];
    int   mx[4];
#pragma unroll
    for (int q = 0; q < 4; q++) {
        rg[q]  = g_rg[t + q * 256];
        mx[q]  = g_colmax[t + q * 256];
        acc[q] = 0.f;
    }
    for (int r = r0; r < r0 + 32; r++) {
        const int16_t* row = &g_s[(size_t)r * N3];
#pragma unroll
        for (int q = 0; q < 4; q++)
            acc[q] += expf(rg[q] * (float)(row[t + q * 256] - mx[q]));
    }
#pragma unroll
    for (int q = 0; q < 4; q++) atomicAdd(&g_Z[t + q * 256], acc[q]);
}

__global__ void bp_invz() {
    int j = blockIdx.x * blockDim.x + threadIdx.x;
    if (j < N3) g_invZ[j] = 1.f / g_Z[j];
}

// ---------------- writeout (row-major, fully coalesced) --------------------
__global__ void bp_writeout(float* __restrict__ out) {
    size_t e = (size_t)blockIdx.x * blockDim.x + threadIdx.x;
    int j = (int)(e & (N3 - 1));
    out[e] = expf(g_rg[j] * (float)(g_s[e] - g_colmax[j])) * g_invZ[j];
}

// ---------------- launch ---------------------------------------------------
extern "C" void kernel_launch(void* const* d_in, const int* in_sizes, int n_in,
                              void* d_out, int out_size) {
    const float* x     = (const float*)d_in[0];
    const float* W0    = (const float*)d_in[1];
    const float* W1    = (const float*)d_in[2];
    const float* W2    = (const float*)d_in[3];
    const float* gamma = (const float*)d_in[4];
    const float* beta  = (const float*)d_in[5];
    float* out = (float*)d_out;

    cudaFuncSetAttribute(bp_hmma, cudaFuncAttributeMaxDynamicSharedMemorySize, SMEM_TOTAL);

    dim3 b32(32, 32);
    bp_binx<<<(BATCH * KBITS / 4) / 256, 256>>>(x);
    bp_binw<<<dim3(N12 / 32, KBITS / 32), b32>>>(W0, 0, N12);
    bp_binw<<<dim3(N12 / 32, KBITS / 32), b32>>>(W1, 1, N12);
    bp_binw<<<dim3(N3  / 32, KBITS / 32), b32>>>(W2, 2, N3);

    // ---- layer 0 ----
    bp_zero<<<N12 / 256, 256>>>(N12);
    bp_hmma<<<dim3(N12 / BN, BATCH / BM), 256, SMEM_TOTAL>>>(0, 0, N12, 0);
    bp_colprep<<<N12 / 256, 256>>>(N12, gamma, 0);
    bp_bins<<<(BATCH * N12 / 8) / 256, 256>>>(N12, 1, beta, 0);

    // ---- layer 1 ----
    bp_zero<<<N12 / 256, 256>>>(N12);
    bp_hmma<<<dim3(N12 / BN, BATCH / BM), 256, SMEM_TOTAL>>>(1, 1, N12, 0);
    bp_colprep<<<N12 / 256, 256>>>(N12, gamma, 1);
    bp_bins<<<(BATCH * N12 / 8) / 256, 256>>>(N12, 0, beta, 1);

    // ---- layer 2 (row-major s, +colmax) ----
    bp_zero<<<N12 / 256, 256>>>(N12);
    bp_hmma<<<dim3(N3 / BN, BATCH / BM), 256, SMEM_TOTAL>>>(0, 2, N3, 1);
    bp_colprep<<<N3 / 256, 256>>>(N3, gamma, 2);
    bp_softz<<<256, 256>>>();
    bp_invz<<<N3 / 256, 256>>>();
    bp_writeout<<<(BATCH * N3) / 256, 256>>>(out);
}